// round 5
// baseline (speedup 1.0000x reference)
#include <cuda_runtime.h>
#include <cstdint>

// Fixed problem geometry: H=W=2048, step=2 -> nu=nv=1024, N=2^20 nodes.
constexpr int NU = 1024;
constexpr int NV = 1024;
constexpr int N  = NU * NV;
constexpr int W  = 2048;

// Output layout: pts[3N] nrm[3N] radii[N] lens[4N] areas[2N]
constexpr long long OFF_PTS  = 0;
constexpr long long OFF_NRM  = 3LL * N;
constexpr long long OFF_RAD  = 6LL * N;
constexpr long long OFF_LEN  = 7LL * N;
constexpr long long OFF_AREA = 11LL * N;

constexpr int ROWS = 4;            // grid rows per block -> grid = 256 blocks

// Fast sqrt: MUFU.RSQ + FMUL; x==0 -> 0 (guard avoids NaN).
__device__ __forceinline__ float fast_sqrt(float x) {
    return x * rsqrtf(fmaxf(x, 1e-30f));
}

struct F3 { float x, y, z; };

__device__ __forceinline__ F3 loadA(const float* __restrict__ p, int jv, int iu) {
    // anchor (iu, jv): element offset = ((2jv)*W + 2iu)*3 -> 8B aligned
    long long off = ((long long)(2 * jv) * W + 2 * iu) * 3;
    float2 ab = *reinterpret_cast<const float2*>(p + off);
    F3 r; r.x = ab.x; r.y = ab.y; r.z = p[off + 2];
    return r;
}

__device__ __forceinline__ float dist3(const F3& a, const F3& b) {
    float dx = a.x - b.x, dy = a.y - b.y, dz = a.z - b.z;
    return fast_sqrt(dx * dx + dy * dy + dz * dz);
}

// ---------------------------------------------------------------------------
// One block = one full grid row (1024 threads), marching ROWS rows downward.
// Each node computes only its own 4 edges; radii's other 4 incident edges are
// read from smem (current-row left neighbor + previous-row ping-pong buffer).
// sD[buf][d][col+1]: d 0=dR 1=dG 2=dD 3=dAo.
// ---------------------------------------------------------------------------
__global__ __launch_bounds__(NU, 1)
void k_rows(const float* __restrict__ cand,
            const float* __restrict__ cnrm,
            float* __restrict__ out) {
    __shared__ float sD[2][4][NU + 1];

    const int t   = threadIdx.x;          // iu
    const int jv0 = blockIdx.x * ROWS;
    const bool le = t > 0;
    const bool re = t < (NU - 1);

    // center row (jv0) anchors in registers
    F3 pC  = loadA(cand, jv0, t);
    F3 pCr = re ? loadA(cand, jv0, t + 1) : pC;

    // prologue: previous row-pair distances (jv0-1, jv0) into buffer 1
    if (jv0 > 0) {
        F3 pP  = loadA(cand, jv0 - 1, t);
        F3 pPr = re ? loadA(cand, jv0 - 1, t + 1) : pP;
        sD[1][1][t + 1] = dist3(pP, pCr);   // dG_prev
        sD[1][2][t + 1] = dist3(pP, pC);    // dD_prev
        sD[1][3][t + 1] = dist3(pPr, pC);   // dAo_prev
    }
    __syncthreads();

    int buf = 0;
    #pragma unroll
    for (int r = 0; r < ROWS; r++) {
        const int  jv = jv0 + r;
        const bool de = jv < (NV - 1);
        const bool ue = jv > 0;
        const bool rd = re && de;
        const int  k  = jv * NU + t;

        // down row anchors (clamped; flag-guarded)
        F3 pD  = de        ? loadA(cand, jv + 1, t)     : pC;
        F3 pDr = (de && re) ? loadA(cand, jv + 1, t + 1) : pD;
        // own normal
        F3 nr = loadA(cnrm, jv, t);

        // own 4 edge distances
        float dR  = dist3(pC,  pCr);
        float dG  = dist3(pC,  pDr);
        float dD  = dist3(pC,  pD);
        float dAo = dist3(pCr, pD);

        // publish for neighbors
        sD[buf][0][t + 1] = dR;
        sD[buf][1][t + 1] = dG;
        sD[buf][2][t + 1] = dD;
        sD[buf][3][t + 1] = dAo;

        // areas (registers only)
        float e1x = pCr.x - pC.x, e1y = pCr.y - pC.y, e1z = pCr.z - pC.z;
        float e2x = pDr.x - pC.x, e2y = pDr.y - pC.y, e2z = pDr.z - pC.z;
        float f2x = pD.x  - pC.x, f2y = pD.y  - pC.y, f2z = pD.z  - pC.z;
        float cx = e1y * e2z - e1z * e2y;
        float cy = e1z * e2x - e1x * e2z;
        float cz = e1x * e2y - e1y * e2x;
        float gx = e2y * f2z - e2z * f2y;
        float gy = e2z * f2x - e2x * f2z;
        float gz = e2x * f2y - e2y * f2x;
        float a0 = 0.5f * fast_sqrt(cx * cx + cy * cy + cz * cz + 1e-13f);
        float a1 = 0.5f * fast_sqrt(gx * gx + gy * gy + gz * gz + 1e-13f);

        __syncthreads();

        // shared incident edges
        float dRl  = sD[buf][0][t];          // right(k-1)
        float dAol = sD[buf][3][t];          // anti(k-1)
        float dGpl = sD[buf ^ 1][1][t];      // diag(k-NU-1)
        float dDp  = sD[buf ^ 1][2][t + 1];  // down(k-NU)
        float dAop = sD[buf ^ 1][3][t + 1];  // anti(k-NU)

        float sum = 0.0f; int cnt = 0;
        if (re)       { sum += dR;   cnt++; }
        if (rd)       { sum += dG;   cnt++; }
        if (de)       { sum += dD;   cnt++; }
        if (le && de) { sum += dAol; cnt++; }
        if (le)       { sum += dRl;  cnt++; }
        if (le && ue) { sum += dGpl; cnt++; }
        if (ue)       { sum += dDp;  cnt++; }
        if (re && ue) { sum += dAop; cnt++; }

        // ---- outputs ----
        float* po = out + OFF_PTS + 3LL * k;
        po[0] = pC.x; po[1] = pC.y; po[2] = pC.z;
        float* no = out + OFF_NRM + 3LL * k;
        no[0] = nr.x; no[1] = nr.y; no[2] = nr.z;
        out[OFF_RAD + k] = sum / (float)max(cnt, 1);
        out[OFF_LEN + 0LL * N + k] = re ? dR  : 0.0f;
        out[OFF_LEN + 1LL * N + k] = rd ? dG  : 0.0f;
        out[OFF_LEN + 2LL * N + k] = de ? dD  : 0.0f;
        out[OFF_LEN + 3LL * N + k] = rd ? dAo : 0.0f;
        out[OFF_AREA + 0LL * N + k] = rd ? a0 : 0.0f;
        out[OFF_AREA + 1LL * N + k] = rd ? a1 : 0.0f;

        __syncthreads();   // WAR guard before next iter overwrites buf^1

        buf ^= 1;
        pC = pD; pCr = pDr;
    }
}

// ---------------------------------------------------------------------------
// Launch
// ---------------------------------------------------------------------------
extern "C" void kernel_launch(void* const* d_in, const int* in_sizes, int n_in,
                              void* d_out, int out_size) {
    (void)in_sizes; (void)n_in; (void)out_size;
    const float* cand = (const float*)d_in[1];
    const float* cnrm = (const float*)d_in[2];
    float* out = (float*)d_out;

    k_rows<<<NV / ROWS, NU>>>(cand, cnrm, out);
}

// round 6
// speedup vs baseline: 1.2072x; 1.2072x over previous
#include <cuda_runtime.h>
#include <cstdint>

// Fixed problem geometry: H=W=2048, step=2 -> nu=nv=1024, N=2^20 nodes.
constexpr int NU = 1024;
constexpr int NV = 1024;
constexpr int N  = NU * NV;
constexpr int W  = 2048;

// Output layout: pts[3N] nrm[3N] radii[N] lens[4N] areas[2N]
constexpr long long OFF_PTS  = 0;
constexpr long long OFF_NRM  = 3LL * N;
constexpr long long OFF_RAD  = 6LL * N;
constexpr long long OFF_LEN  = 7LL * N;
constexpr long long OFF_AREA = 11LL * N;

constexpr int TX = 32;   // tile width  (lane = x)
constexpr int TY = 8;    // tile height

// Fast sqrt: MUFU.RSQ + FMUL; x==0 -> 0 (guard avoids NaN).
__device__ __forceinline__ float fast_sqrt(float x) {
    return x * rsqrtf(fmaxf(x, 1e-30f));
}

struct F3 { float x, y, z; };

__device__ __forceinline__ F3 loadA(const float* __restrict__ p, int jv, int iu) {
    // anchor (iu, jv): element offset = ((2jv)*W + 2iu)*3 -> 8B aligned
    long long off = ((long long)(2 * jv) * W + 2 * iu) * 3;
    float2 ab = *reinterpret_cast<const float2*>(p + off);
    F3 r; r.x = ab.x; r.y = ab.y; r.z = p[off + 2];
    return r;
}

__device__ __forceinline__ float dist3(const F3& a, const F3& b) {
    float dx = a.x - b.x, dy = a.y - b.y, dz = a.z - b.z;
    return fast_sqrt(dx * dx + dy * dy + dz * dz);
}

// ---------------------------------------------------------------------------
// 32x8 tile per 256-thread block. Each thread computes ONLY its 4 owned edge
// distances (+2 areas); the 4 other radii terms come from smem, including a
// halo row (above tile) and halo column (left of tile) computed by y==0 /
// x==0 threads. Distances at clamped positions are garbage but flag-guarded.
// smem dist arrays indexed [yy][xx], yy=y+1, xx=x+1 (0 = halo).
// ---------------------------------------------------------------------------
__global__ __launch_bounds__(TX * TY)
void k_tile(const float* __restrict__ cand,
            const float* __restrict__ cnrm,
            float* __restrict__ out) {
    __shared__ float sR [TY + 1][TX + 1];   // dR  = |p(k)   - p(k+1)|
    __shared__ float sG [TY + 1][TX + 1];   // dG  = |p(k)   - p(k+NU+1)|
    __shared__ float sDv[TY + 1][TX + 1];   // dD  = |p(k)   - p(k+NU)|
    __shared__ float sA [TY + 1][TX + 1];   // dAo = |p(k+1) - p(k+NU)|

    const int x   = threadIdx.x & (TX - 1);
    const int y   = threadIdx.x >> 5;
    const int iu0 = blockIdx.x * TX;
    const int jv0 = blockIdx.y * TY;
    const int iu  = iu0 + x;
    const int jv  = jv0 + y;
    const int k   = jv * NU + iu;

    const bool re = iu < NU - 1;
    const bool de = jv < NV - 1;
    const bool le = iu > 0;
    const bool ue = jv > 0;
    const bool rd = re && de;

    const int iuR = min(iu + 1, NU - 1);
    const int jvD = min(jv + 1, NV - 1);

    // own 2x2 point window + normal
    F3 p0 = loadA(cand, jv,  iu);
    F3 pR = loadA(cand, jv,  iuR);
    F3 pD = loadA(cand, jvD, iu);
    F3 pG = loadA(cand, jvD, iuR);
    F3 nr = loadA(cnrm, jv,  iu);

    // owned distances
    float dR  = dist3(p0, pR);
    float dG  = dist3(p0, pG);
    float dD  = dist3(p0, pD);
    float dAo = dist3(pR, pD);

    sR [y + 1][x + 1] = dR;
    sG [y + 1][x + 1] = dG;
    sDv[y + 1][x + 1] = dD;
    sA [y + 1][x + 1] = dAo;

    // top halo (row jv0-1), computed by y==0 warp; entry xx = x+1
    if (y == 0) {
        int jvU = max(jv0 - 1, 0);
        F3 pU  = loadA(cand, jvU, iu);
        F3 pUR = loadA(cand, jvU, iuR);
        sG [0][x + 1] = dist3(pU,  pR);   // dG (iu, jv0-1)
        sDv[0][x + 1] = dist3(pU,  p0);   // dD (iu, jv0-1)
        sA [0][x + 1] = dist3(pUR, p0);   // dAo(iu, jv0-1)
    }
    // left halo (col iu0-1), computed by x==0 threads; entry yy = y+1
    if (x == 0) {
        int iuL = max(iu0 - 1, 0);
        F3 pL  = loadA(cand, jv,  iuL);
        F3 pDL = loadA(cand, jvD, iuL);
        sR[y + 1][0] = dist3(pL, p0);     // dR (iu0-1, jv)
        sG[y + 1][0] = dist3(pL, pD);     // dG (iu0-1, jv)
        sA[y + 1][0] = dist3(p0, pDL);    // dAo(iu0-1, jv)
    }
    // corner: dG(iu0-1, jv0-1), read by thread (0,0)
    if (threadIdx.x == 0) {
        int iuL = max(iu0 - 1, 0);
        int jvU = max(jv0 - 1, 0);
        F3 pUL = loadA(cand, jvU, iuL);
        sG[0][0] = dist3(pUL, p0);
    }

    // areas (registers only; independent of smem)
    float e1x = pR.x - p0.x, e1y = pR.y - p0.y, e1z = pR.z - p0.z;
    float e2x = pG.x - p0.x, e2y = pG.y - p0.y, e2z = pG.z - p0.z;
    float f2x = pD.x - p0.x, f2y = pD.y - p0.y, f2z = pD.z - p0.z;
    float cx = e1y * e2z - e1z * e2y;
    float cy = e1z * e2x - e1x * e2z;
    float cz = e1x * e2y - e1y * e2x;
    float gx = e2y * f2z - e2z * f2y;
    float gy = e2z * f2x - e2x * f2z;
    float gz = e2x * f2y - e2y * f2x;
    float a0 = 0.5f * fast_sqrt(cx * cx + cy * cy + cz * cz + 1e-13f);
    float a1 = 0.5f * fast_sqrt(gx * gx + gy * gy + gz * gz + 1e-13f);

    __syncthreads();

    // shared incident edges
    float dRl  = sR [y + 1][x];      // right(k-1)
    float dAol = sA [y + 1][x];      // anti (k-1)
    float dGul = sG [y][x];          // diag (k-NU-1)
    float dDu  = sDv[y][x + 1];      // down (k-NU)
    float dAou = sA [y][x + 1];      // anti (k-NU)

    float sum = 0.0f; int cnt = 0;
    if (re)       { sum += dR;   cnt++; }
    if (rd)       { sum += dG;   cnt++; }
    if (de)       { sum += dD;   cnt++; }
    if (le && de) { sum += dAol; cnt++; }
    if (le)       { sum += dRl;  cnt++; }
    if (le && ue) { sum += dGul; cnt++; }
    if (ue)       { sum += dDu;  cnt++; }
    if (re && ue) { sum += dAou; cnt++; }

    // ---- outputs ----
    float* po = out + OFF_PTS + 3LL * k;
    po[0] = p0.x; po[1] = p0.y; po[2] = p0.z;
    float* no = out + OFF_NRM + 3LL * k;
    no[0] = nr.x; no[1] = nr.y; no[2] = nr.z;
    out[OFF_RAD + k] = sum / (float)max(cnt, 1);
    out[OFF_LEN + 0LL * N + k] = re ? dR  : 0.0f;
    out[OFF_LEN + 1LL * N + k] = rd ? dG  : 0.0f;
    out[OFF_LEN + 2LL * N + k] = de ? dD  : 0.0f;
    out[OFF_LEN + 3LL * N + k] = rd ? dAo : 0.0f;
    out[OFF_AREA + 0LL * N + k] = rd ? a0 : 0.0f;
    out[OFF_AREA + 1LL * N + k] = rd ? a1 : 0.0f;
}

// ---------------------------------------------------------------------------
// Launch
// ---------------------------------------------------------------------------
extern "C" void kernel_launch(void* const* d_in, const int* in_sizes, int n_in,
                              void* d_out, int out_size) {
    (void)in_sizes; (void)n_in; (void)out_size;
    const float* cand = (const float*)d_in[1];
    const float* cnrm = (const float*)d_in[2];
    float* out = (float*)d_out;

    dim3 grid(NU / TX, NV / TY);
    k_tile<<<grid, TX * TY>>>(cand, cnrm, out);
}